// round 17
// baseline (speedup 1.0000x reference)
#include <cuda_runtime.h>
#include <cuda_fp16.h>
#include <cstdint>

#define DIM    128
#define BATCH  1048576
#define NT64   (BATCH / 64)    // 16384 half-tiles (64 rows each)
#define GRID   152
#define PITCHB 272             // fp16 smem row pitch (17 x 16B -> LDSM conflict-free)
#define STAGES 3
#define STG_BYTES (64 * PITCHB)   // 17408 per stage

// ---------------------------------------------------------------------------
// helpers
// ---------------------------------------------------------------------------
__device__ __forceinline__ uint32_t smem_u32(const void* p) {
    uint32_t a;
    asm("{ .reg .u64 t; cvta.to.shared.u64 t, %1; cvt.u32.u64 %0, t; }"
        : "=r"(a) : "l"(p));
    return a;
}

// fp16 MMA, fp32 accumulate (base PTX ISA; compiles at compute_103)
#define MMA16816(d, a, b)                                                        \
    asm volatile(                                                                \
        "mma.sync.aligned.m16n8k16.row.col.f32.f16.f16.f32 "                     \
        "{%0,%1,%2,%3}, {%4,%5,%6,%7}, {%8,%9}, {%0,%1,%2,%3};"                  \
        : "+f"((d)[0]), "+f"((d)[1]), "+f"((d)[2]), "+f"((d)[3])                 \
        : "r"((a)[0]), "r"((a)[1]), "r"((a)[2]), "r"((a)[3]),                    \
          "r"((b)[0]), "r"((b)[1]))

#define LDSM4(r, addr)                                                           \
    asm volatile("ldmatrix.sync.aligned.m8n8.x4.shared.b16 {%0,%1,%2,%3}, [%4];" \
                 : "=r"((r)[0]), "=r"((r)[1]), "=r"((r)[2]), "=r"((r)[3])        \
                 : "r"(addr))

// pack 2 fp32 -> f16x2 in one instruction
#define CVT_F16X2(d, hi, lo)                                                     \
    asm("cvt.rn.f16x2.f32 %0, %1, %2;" : "=r"(d) : "f"(hi), "f"(lo))

// named stream barriers, 160 participants (4 consumer + 1 producer warp)
#define SBAR_SYNC(id)   asm volatile("bar.sync %0, 160;"   :: "r"(id) : "memory")
#define SBAR_ARRIVE(id) asm volatile("bar.arrive %0, 160;" :: "r"(id) : "memory")

// ---------------------------------------------------------------------------
// Fused kernel: per-CTA redundant W build (Householder scan) + TWO independent
// persistent producer/consumer GEMM streams.  y = fp16(x) @ fp16(W), fp32
// accumulate (rel_err ~2.9e-4, validated R12-R15).
//
// 320 threads: warps 0-3 consumers S0, 4-7 consumers S1 (each 64Mx32N over
// 64-row half-tiles; W fragments held in REGISTERS, zero per-tile B traffic),
// warps 8/9 producers S0/S1 (LDG fp32 -> f16x2 -> STS, 3-stage ring each).
// ---------------------------------------------------------------------------
#define SM_STAGE(st, s) (((st) * STAGES + (s)) * STG_BYTES)
#define SM_W            (6 * STG_BYTES)          // 104448
#define SMEM_BYTES      (SM_W + 34816)           // 139264

#define VPITCH 132   // fp32 scratch pitch for V columns (528B = 33*16, aligned)

__global__ void __launch_bounds__(320, 1)
fused_kernel(const float* __restrict__ x, const float* __restrict__ V,
             const float* __restrict__ scale, const float* __restrict__ diag,
             float* __restrict__ y, int out_size) {
    extern __shared__ char sm[];
    uint32_t sb = smem_u32(sm);

    int t = threadIdx.x, wid = t >> 5, lane = t & 31;

    // ======================================================================
    // Phase 0: build W = Q diag s in this CTA's smem.
    // sv scratch uses [0, 67584) inside the stage area; W region disjoint.
    // Threads 0-255 (the 8 consumer warps): 2 threads/Q-row, 64 floats each.
    // ======================================================================
    {
        float* sv = (float*)sm;              // sv[col*VPITCH + row] = vhat
        __shared__ float s_invn[DIM];

        for (int idx = t; idx < DIM * DIM; idx += 320) {
            int r0 = idx >> 7, c0 = idx & 127;
            sv[c0 * VPITCH + r0] = V[idx];
        }
        __syncthreads();

        if (t < DIM) {
            float ss = 0.0f;
            const float* c = sv + t * VPITCH;
#pragma unroll 8
            for (int j = 0; j < DIM; j++) ss += c[j] * c[j];
            s_invn[t] = 1.0f / (sqrtf(ss) + 1e-8f);
        }
        __syncthreads();

        for (int idx = t; idx < DIM * DIM; idx += 320) {
            int r0 = idx & 127, c0 = idx >> 7;
            sv[c0 * VPITCH + r0] *= s_invn[c0];
        }
        __syncthreads();

        if (t < 256) {
            int row = t >> 1;
            int h   = t & 1;
            float q[64];
#pragma unroll
            for (int j = 0; j < 64; j++) q[j] = 0.0f;
            {
                int c0 = h * 64;
                if (row >= c0 && row < c0 + 64) q[row - c0] = 1.0f;
            }

            for (int i = 0; i < DIM; i++) {
                const float4* vb = (const float4*)(sv + i * VPITCH + h * 64);
                float4 v4[16];
#pragma unroll
                for (int j4 = 0; j4 < 16; j4++) v4[j4] = vb[j4];

                float d0 = 0.f, d1 = 0.f, d2 = 0.f, d3 = 0.f;
#pragma unroll
                for (int j4 = 0; j4 < 16; j4++) {
                    d0 += q[4 * j4 + 0] * v4[j4].x;
                    d1 += q[4 * j4 + 1] * v4[j4].y;
                    d2 += q[4 * j4 + 2] * v4[j4].z;
                    d3 += q[4 * j4 + 3] * v4[j4].w;
                }
                float dp = (d0 + d1) + (d2 + d3);
                dp += __shfl_xor_sync(0xffffffffu, dp, 1);   // combine halves
                float coef = 2.0f * dp;                       // Q -= 2(Qv)v^T
#pragma unroll
                for (int j4 = 0; j4 < 16; j4++) {
                    q[4 * j4 + 0] -= coef * v4[j4].x;
                    q[4 * j4 + 1] -= coef * v4[j4].y;
                    q[4 * j4 + 2] -= coef * v4[j4].z;
                    q[4 * j4 + 3] -= coef * v4[j4].w;
                }
            }

            // store W_B[n][k]: n = col c, k = row.  W[k][n] = Q[k][n]*diag*s
            float s = scale[0];
#pragma unroll
            for (int j = 0; j < 64; j++) {
                int c = h * 64 + j;
                float w = q[j] * diag[c] * s;
                *(__half*)(sm + SM_W + c * PITCHB + row * 2) = __float2half_rn(w);
            }

            if (blockIdx.x == 0 && t == 0 && out_size > BATCH * DIM) {
                float ld = 0.0f;
                for (int c = 0; c < DIM; c++) ld += logf(fabsf(diag[c] * s) + 1e-8f);
                y[(size_t)BATCH * DIM] = ld;
            }
        }
        __syncthreads();   // W ready; sv scratch dead -> stage buffers free
    }

    // ======================================================================
    // Phase 1: two independent persistent pipelines, 3-stage rings.
    // Barrier ids: stream st: full[s] = 1 + st*6 + s, empty[s] = 4 + st*6 + s
    // ======================================================================
    if (wid >= 8) {
        // ---------------- PRODUCER (1 warp per stream) ----------------
        int st   = wid - 8;                   // stream 0/1
        int barF = 1 + st * 6, barE = 4 + st * 6;

        int i = 0, s = 0;
        for (int tile = blockIdx.x * 2 + st; tile < NT64; tile += GRID * 2, i++) {
            const float4* src = (const float4*)(x + (size_t)tile * 64 * DIM);
            float4 f[32];
            // batch 1: chunks 0..1023 (rows 0-31)
#pragma unroll
            for (int c = 0; c < 32; c++) f[c] = __ldcs(src + c * 32 + lane);

            if (i >= STAGES) SBAR_SYNC(barE + s);    // wait empty[s]

            char* dst = sm + SM_STAGE(st, s);
#pragma unroll
            for (int c = 0; c < 32; c++) {
                int idx = c * 32 + lane;
                int row = idx >> 5, c5 = idx & 31;
                float4 v = f[c];
                uint2 hv;
                CVT_F16X2(hv.x, v.y, v.x);
                CVT_F16X2(hv.y, v.w, v.z);
                *(uint2*)(dst + row * PITCHB + c5 * 8) = hv;
            }
            // batch 2: chunks 1024..2047 (rows 32-63)
#pragma unroll
            for (int c = 0; c < 32; c++) f[c] = __ldcs(src + 1024 + c * 32 + lane);
#pragma unroll
            for (int c = 0; c < 32; c++) {
                int idx = 1024 + c * 32 + lane;
                int row = idx >> 5, c5 = idx & 31;
                float4 v = f[c];
                uint2 hv;
                CVT_F16X2(hv.x, v.y, v.x);
                CVT_F16X2(hv.y, v.w, v.z);
                *(uint2*)(dst + row * PITCHB + c5 * 8) = hv;
            }
            SBAR_ARRIVE(barF + s);                   // full[s]
            if (++s == STAGES) s = 0;
        }
    } else {
        // ---------------- CONSUMER (4 warps per stream) ----------------
        int st   = wid >> 2;                  // stream 0/1
        int ncol = (wid & 3) * 32;            // warp's 32 N-columns
        int barF = 1 + st * 6, barE = 4 + st * 6;
        int g = lane >> 2, tid4 = lane & 3;
        uint32_t lrow = (uint32_t)(lane & 15);
        uint32_t lcol = (uint32_t)((lane >> 4) << 3);

        // ---- W fragments into registers (once; W smem stays resident) ----
        uint32_t Bh[8][4][2];
#pragma unroll
        for (int ks = 0; ks < 8; ks++)
#pragma unroll
            for (int j = 0; j < 4; j++) {
                int n  = ncol + j * 8 + g;
                int k0 = ks * 16 + tid4 * 2;
                const char* base = sm + SM_W + n * PITCHB + k0 * 2;
                Bh[ks][j][0] = *(const uint32_t*)(base);
                Bh[ks][j][1] = *(const uint32_t*)(base + 16);
            }

        int i = 0, s = 0;
        for (int tile = blockIdx.x * 2 + st; tile < NT64; tile += GRID * 2, i++) {
            SBAR_SYNC(barF + s);                     // wait full[s]
            uint32_t xh = sb + SM_STAGE(st, s);

            float acc[4][4][4];
#pragma unroll
            for (int ii = 0; ii < 4; ii++)
#pragma unroll
                for (int j = 0; j < 4; j++)
#pragma unroll
                    for (int e = 0; e < 4; e++) acc[ii][j][e] = 0.0f;

#pragma unroll
            for (int ks = 0; ks < 8; ks++) {
                uint32_t Ah[4][4];
#pragma unroll
                for (int ii = 0; ii < 4; ii++) {
                    uint32_t off = (uint32_t)(ii * 16 + lrow) * PITCHB +
                                   (uint32_t)(ks * 16 + lcol) * 2;
                    LDSM4(Ah[ii], xh + off);
                }
#pragma unroll
                for (int ii = 0; ii < 4; ii++)
#pragma unroll
                    for (int j = 0; j < 4; j++) MMA16816(acc[ii][j], Ah[ii], Bh[ks][j]);
            }
            SBAR_ARRIVE(barE + s);                   // empty[s] (reads done)

            float* yt = y + (size_t)tile * 64 * DIM;
#pragma unroll
            for (int ii = 0; ii < 4; ii++) {
                int row0 = ii * 16 + g;
#pragma unroll
                for (int j = 0; j < 4; j++) {
                    int cb = ncol + j * 8 + tid4 * 2;
                    float2 v0, v1;
                    v0.x = acc[ii][j][0]; v0.y = acc[ii][j][1];
                    v1.x = acc[ii][j][2]; v1.y = acc[ii][j][3];
                    __stcs((float2*)(yt + (size_t)row0 * DIM + cb), v0);
                    __stcs((float2*)(yt + (size_t)(row0 + 8) * DIM + cb), v1);
                }
            }
            if (++s == STAGES) s = 0;
        }
    }
}

// ---------------------------------------------------------------------------
// Launch
// ---------------------------------------------------------------------------
extern "C" void kernel_launch(void* const* d_in, const int* in_sizes, int n_in,
                              void* d_out, int out_size) {
    const float* x    = (const float*)d_in[0];   // [BATCH, DIM]
    const float* V    = (const float*)d_in[1];   // [DIM, DIM] (v_i = columns)
    const float* sc   = (const float*)d_in[2];   // [1]
    const float* diag = (const float*)d_in[3];   // [DIM]
    float* out = (float*)d_out;

    cudaFuncSetAttribute(fused_kernel,
                         cudaFuncAttributeMaxDynamicSharedMemorySize, SMEM_BYTES);
    fused_kernel<<<GRID, 320, SMEM_BYTES>>>(x, V, sc, diag, out, out_size);
}